// round 1
// baseline (speedup 1.0000x reference)
#include <cuda_runtime.h>
#include <math.h>

#define B_   8192
#define IN_  4096
#define H_   1024
#define P_   2048
#define NW_  3
#define NC_  1000
#define H2_  2048

// ---------------- scratch (static device globals; no allocation) ----------------
__device__ float d_h   [(size_t)B_ * P_];            // GEMM1 out -> LN+gelu in place
__device__ float d_out2[(size_t)B_ * NW_ * H2_];     // wave GEMM out
__device__ float d_supr[(size_t)B_ * H_];
__device__ float d_supi[(size_t)B_ * H_];
__device__ float d_magA[(size_t)B_ * H_];
__device__ float d_magB[(size_t)B_ * H_];
__device__ float d_prob[(size_t)B_ * H_];
__device__ float d_t1  [(size_t)B_ * H_];
__device__ float d_su[NW_ * P_];
__device__ float d_sv[NW_ * P_];
__device__ float d_st[NW_ * P_];
__device__ float d_sigma_inv[NW_];

// ---------------- helpers ----------------
__device__ __forceinline__ float gelu_f(float x) {
    return 0.5f * x * (1.f + erff(x * 0.70710678118654752440f));
}

__device__ __forceinline__ float blockReduceSum(float v) {
    __shared__ float sh[33];
    int lane = threadIdx.x & 31;
    int wid  = threadIdx.x >> 5;
    #pragma unroll
    for (int o = 16; o; o >>= 1) v += __shfl_xor_sync(0xffffffffu, v, o);
    __syncthreads();               // protect sh across repeated calls
    if (lane == 0) sh[wid] = v;
    __syncthreads();
    if (wid == 0) {
        int nw = (blockDim.x + 31) >> 5;
        float r = (lane < nw) ? sh[lane] : 0.f;
        #pragma unroll
        for (int o = 16; o; o >>= 1) r += __shfl_xor_sync(0xffffffffu, r, o);
        if (lane == 0) sh[32] = r;
    }
    __syncthreads();
    return sh[32];
}

// ---------------- generic SGEMM with fused epilogues ----------------
// C[M,N] = A[M,K] @ B[K,N]  (both row-major), per-z batch offsets for B/bias/C.
// EPI: 0 = +bias store; 1 = *sigma_inv[z] +bias store; 2 = sigmoid gate update; 3 = gelu(+bias) store
#define BM 128
#define BN 128
#define BK 8
#define TM 8
#define TN 8

template<int EPI, bool GUARD>
__global__ void __launch_bounds__(256)
sgemm_k(const float* __restrict__ A, const float* __restrict__ B, float* __restrict__ C,
        int M, int N, int K, int ldc,
        const float* __restrict__ bias,
        long long bStrideZ, long long biasStrideZ, long long cOffZ,
        float* __restrict__ supr, float* __restrict__ supi, float* __restrict__ magout)
{
    __shared__ float As[BK][BM];
    __shared__ float Bs[BK][BN];

    const int z = blockIdx.z;
    const float* Bp    = B    + (size_t)z * bStrideZ;
    const float* biasp = bias + (size_t)z * biasStrideZ;
    float*       Cp    = C    + (size_t)z * cOffZ;

    const int tid  = threadIdx.x;
    const int brow = blockIdx.y * BM;
    const int bcol = blockIdx.x * BN;

    const int aRow = tid >> 1;
    const int aCol = (tid & 1) * 4;
    const int bRow = tid >> 5;
    const int bCol = (tid & 31) * 4;

    const int tr = (tid >> 4) * TM;
    const int tc = (tid & 15) * TN;

    float acc[TM][TN];
    #pragma unroll
    for (int i = 0; i < TM; i++)
        #pragma unroll
        for (int j = 0; j < TN; j++) acc[i][j] = 0.f;

    const float* Aptr = A + (size_t)(brow + aRow) * K + aCol;

    for (int k0 = 0; k0 < K; k0 += BK) {
        float4 av = *(const float4*)(Aptr + k0);
        As[aCol + 0][aRow] = av.x;
        As[aCol + 1][aRow] = av.y;
        As[aCol + 2][aRow] = av.z;
        As[aCol + 3][aRow] = av.w;
        if (!GUARD) {
            float4 bv = *(const float4*)(Bp + (size_t)(k0 + bRow) * N + (bcol + bCol));
            *(float4*)&Bs[bRow][bCol] = bv;
        } else {
            #pragma unroll
            for (int q = 0; q < 4; q++) {
                int col = bcol + bCol + q;
                Bs[bRow][bCol + q] = (col < N) ? Bp[(size_t)(k0 + bRow) * N + col] : 0.f;
            }
        }
        __syncthreads();
        #pragma unroll
        for (int kk = 0; kk < BK; kk++) {
            float ar[TM], br[TN];
            #pragma unroll
            for (int i = 0; i < TM; i++) ar[i] = As[kk][tr + i];
            #pragma unroll
            for (int j = 0; j < TN; j++) br[j] = Bs[kk][tc + j];
            #pragma unroll
            for (int i = 0; i < TM; i++)
                #pragma unroll
                for (int j = 0; j < TN; j++)
                    acc[i][j] = fmaf(ar[i], br[j], acc[i][j]);
        }
        __syncthreads();
    }

    float scale = 1.f;
    if (EPI == 1) scale = d_sigma_inv[z];

    #pragma unroll
    for (int i = 0; i < TM; i++) {
        int row = brow + tr + i;
        #pragma unroll
        for (int j = 0; j < TN; j++) {
            int col = bcol + tc + j;
            if (GUARD && col >= N) continue;
            float v = acc[i][j] * scale + biasp[col];
            if (EPI == 0 || EPI == 1) {
                Cp[(size_t)row * ldc + col] = v;
            } else if (EPI == 3) {
                Cp[(size_t)row * ldc + col] = gelu_f(v);
            } else if (EPI == 2) {
                float g = 1.f / (1.f + expf(-v));
                float f = g + 0.1f;
                size_t idx = (size_t)row * N + col;
                float r  = supr[idx] * f;
                float ii = supi[idx] * f;
                supr[idx] = r;
                supi[idx] = ii;
                magout[idx] = sqrtf(r * r + ii * ii + 1e-8f);
            }
        }
    }
}

// ---------------- LN + gelu over rows of length 2048, in place ----------------
__global__ void __launch_bounds__(256)
ln_gelu_k(float* __restrict__ h, const float* __restrict__ g, const float* __restrict__ beta)
{
    const int b = blockIdx.x, tid = threadIdx.x;
    float* row = h + (size_t)b * P_;
    float x[8];
    float sm = 0.f;
    #pragma unroll
    for (int t = 0; t < 8; t++) { x[t] = row[tid + t * 256]; sm += x[t]; }
    float mean = blockReduceSum(sm) * (1.f / (float)P_);
    float vs = 0.f;
    #pragma unroll
    for (int t = 0; t < 8; t++) { float d = x[t] - mean; vs += d * d; }
    float var = blockReduceSum(vs) * (1.f / (float)P_);
    float inv = rsqrtf(var + 1e-5f);
    #pragma unroll
    for (int t = 0; t < 8; t++) {
        int j = tid + t * 256;
        float y = (x[t] - mean) * inv * g[j] + beta[j];
        row[j] = gelu_f(y);
    }
}

// ---------------- spectral normalization (power iteration) ----------------
__global__ void sn_init_k(float* __restrict__ u) {
    int z = blockIdx.y;
    int j = blockIdx.x * 256 + threadIdx.x;
    u[z * P_ + j] = 1.f / sqrtf((float)P_);
}

// v_raw = W @ u  (warp per row)
__global__ void __launch_bounds__(256)
sn_mv_Wu_k(const float* __restrict__ W, const float* __restrict__ u, float* __restrict__ out) {
    int z = blockIdx.y;
    const float* Wz = W + (size_t)z * P_ * H2_;
    const float* uz = u + z * P_;
    int warp = threadIdx.x >> 5, lane = threadIdx.x & 31;
    int row = blockIdx.x * 8 + warp;
    const float* wr = Wz + (size_t)row * H2_;
    float s = 0.f;
    for (int k = lane; k < H2_; k += 32) s += wr[k] * uz[k];
    #pragma unroll
    for (int o = 16; o; o >>= 1) s += __shfl_xor_sync(0xffffffffu, s, o);
    if (lane == 0) out[z * P_ + row] = s;
}

// u_raw = W^T @ v  (thread per column)
__global__ void __launch_bounds__(256)
sn_mv_WTv_k(const float* __restrict__ W, const float* __restrict__ v, float* __restrict__ out) {
    __shared__ float vs[P_];
    int z = blockIdx.y;
    const float* Wz = W + (size_t)z * P_ * H2_;
    int j = blockIdx.x * 256 + threadIdx.x;
    for (int i = threadIdx.x; i < P_; i += 256) vs[i] = v[z * P_ + i];
    __syncthreads();
    float s = 0.f;
    #pragma unroll 8
    for (int i = 0; i < P_; i++) s += Wz[(size_t)i * H2_ + j] * vs[i];
    out[z * P_ + j] = s;
}

__global__ void __launch_bounds__(256)
sn_norm_k(float* __restrict__ a) {
    int z = blockIdx.x;
    float s = 0.f;
    for (int i = threadIdx.x; i < P_; i += 256) { float x = a[z * P_ + i]; s += x * x; }
    s = blockReduceSum(s);
    float inv = 1.f / (sqrtf(s) + 1e-12f);
    for (int i = threadIdx.x; i < P_; i += 256) a[z * P_ + i] *= inv;
}

__global__ void __launch_bounds__(256)
sn_sigma_k(const float* __restrict__ v, const float* __restrict__ t) {
    int z = blockIdx.x;
    float s = 0.f;
    for (int i = threadIdx.x; i < P_; i += 256) s += v[z * P_ + i] * t[z * P_ + i];
    s = blockReduceSum(s);
    if (threadIdx.x == 0) d_sigma_inv[z] = 1.f / s;
}

// ---------------- fused wave stage: LN -> exp(-y^2) -> partial norm -> rotate ->
// mean/cos-sim -> softmax(3) -> superposition + mag ----------------
__global__ void __launch_bounds__(256)
wave_k(const float* __restrict__ out2,
       const float* __restrict__ gw, const float* __restrict__ betaw,
       const float* __restrict__ phases, const float* __restrict__ temp,
       float* __restrict__ supr, float* __restrict__ supi, float* __restrict__ mag)
{
    __shared__ float zbuf[H2_];
    __shared__ float wr[NW_][H_];
    __shared__ float wi[NW_][H_];
    __shared__ float mr[H_];
    const int b = blockIdx.x, tid = threadIdx.x;

    for (int s = 0; s < NW_; s++) {
        const float* row = out2 + ((size_t)b * NW_ + s) * H2_;
        float x[8];
        float sm = 0.f;
        #pragma unroll
        for (int t = 0; t < 8; t++) { x[t] = row[tid + t * 256]; sm += x[t]; }
        float mean = blockReduceSum(sm) * (1.f / (float)H2_);
        float vs = 0.f;
        #pragma unroll
        for (int t = 0; t < 8; t++) { float d = x[t] - mean; vs += d * d; }
        float var = blockReduceSum(vs) * (1.f / (float)H2_);
        float inv = rsqrtf(var + 1e-5f);
        float nsq = 0.f;
        #pragma unroll
        for (int t = 0; t < 8; t++) {
            int j = tid + t * 256;
            float y = (x[t] - mean) * inv * gw[s * H2_ + j] + betaw[s * H2_ + j];
            float zz = expf(-y * y);
            zbuf[j] = zz;
            nsq += zz * zz;
        }
        nsq = blockReduceSum(nsq) + 1e-8f;
        float factor = sqrtf(2.25f / nsq);   // PARTIAL_NORM^2 = 1.5^2
        float ph = phases[s];
        float c = cosf(ph), sn = sinf(ph);
        #pragma unroll
        for (int t = 0; t < 4; t++) {
            int h = tid + t * 256;
            float a  = zbuf[h] * factor;
            float be = zbuf[h + H_] * factor;
            wr[s][h] = a * c - be * sn;
            wi[s][h] = a * sn + be * c;
        }
        __syncthreads();
    }

    #pragma unroll
    for (int t = 0; t < 4; t++) {
        int h = tid + t * 256;
        mr[h] = (wr[0][h] + wr[1][h] + wr[2][h]) * (1.f / 3.f);
    }
    __syncthreads();

    float mn = 0.f, n0 = 0.f, n1 = 0.f, n2 = 0.f, d0 = 0.f, d1 = 0.f, d2 = 0.f;
    #pragma unroll
    for (int t = 0; t < 4; t++) {
        int h = tid + t * 256;
        float m = mr[h]; mn += m * m;
        float a0 = wr[0][h]; n0 += a0 * a0; d0 += a0 * m;
        float a1 = wr[1][h]; n1 += a1 * a1; d1 += a1 * m;
        float a2 = wr[2][h]; n2 += a2 * a2; d2 += a2 * m;
    }
    mn = blockReduceSum(mn);
    n0 = blockReduceSum(n0); n1 = blockReduceSum(n1); n2 = blockReduceSum(n2);
    d0 = blockReduceSum(d0); d1 = blockReduceSum(d1); d2 = blockReduceSum(d2);

    float mean_norm = sqrtf(mn) + 1e-8f;
    float cs0 = d0 / ((sqrtf(n0) + 1e-8f) * mean_norm);
    float cs1 = d1 / ((sqrtf(n1) + 1e-8f) * mean_norm);
    float cs2 = d2 / ((sqrtf(n2) + 1e-8f) * mean_norm);
    float invT = 1.f / temp[0];
    float l0 = cs0 * invT, l1 = cs1 * invT, l2 = cs2 * invT;
    float mx = fmaxf(l0, fmaxf(l1, l2));
    float e0 = expf(l0 - mx), e1 = expf(l1 - mx), e2 = expf(l2 - mx);
    float es = e0 + e1 + e2;
    float w0 = e0 / es, w1 = e1 / es, w2 = e2 / es;

    #pragma unroll
    for (int t = 0; t < 4; t++) {
        int h = tid + t * 256;
        float r  = wr[0][h] * w0 + wr[1][h] * w1 + wr[2][h] * w2;
        float ii = wi[0][h] * w0 + wi[1][h] * w1 + wi[2][h] * w2;
        size_t idx = (size_t)b * H_ + h;
        supr[idx] = r;
        supi[idx] = ii;
        mag[idx]  = sqrtf(r * r + ii * ii + 1e-8f);
    }
}

// ---------------- top-8 mask + renormalize -> probs ----------------
__global__ void __launch_bounds__(256)
topk_k(const float* __restrict__ supr, const float* __restrict__ supi, float* __restrict__ probs)
{
    __shared__ float val[H_];
    __shared__ float orig[H_];
    __shared__ float s_bv[8];
    __shared__ int   s_bi[8];
    __shared__ float s_sum;
    const int b = blockIdx.x, tid = threadIdx.x;
    const int lane = tid & 31, wid = tid >> 5;

    #pragma unroll
    for (int t = 0; t < 4; t++) {
        int h = tid + t * 256;
        size_t idx = (size_t)b * H_ + h;
        float r = supr[idx], ii = supi[idx];
        float m = r * r + ii * ii;   // no EPS here (matches reference mag_sq)
        val[h] = m; orig[h] = m;
    }
    if (tid == 0) s_sum = 0.f;
    __syncthreads();

    for (int it = 0; it < 8; it++) {
        float bv = -2.f; int bi = 1 << 30;
        #pragma unroll
        for (int t = 0; t < 4; t++) {
            int h = tid + t * 256;
            float v = val[h];
            if (v > bv) { bv = v; bi = h; }
        }
        #pragma unroll
        for (int o = 16; o; o >>= 1) {
            float ov = __shfl_xor_sync(0xffffffffu, bv, o);
            int   oi = __shfl_xor_sync(0xffffffffu, bi, o);
            if (ov > bv || (ov == bv && oi < bi)) { bv = ov; bi = oi; }
        }
        if (lane == 0) { s_bv[wid] = bv; s_bi[wid] = bi; }
        __syncthreads();
        if (tid == 0) {
            for (int q = 1; q < 8; q++)
                if (s_bv[q] > bv || (s_bv[q] == bv && s_bi[q] < bi)) { bv = s_bv[q]; bi = s_bi[q]; }
            s_sum += bv;
            val[bi] = -1.f;
        }
        __syncthreads();
    }

    float invs = 1.f / (s_sum + 1e-8f);
    #pragma unroll
    for (int t = 0; t < 4; t++) {
        int h = tid + t * 256;
        float p = (val[h] == -1.f) ? orig[h] * invs : 0.f;
        probs[(size_t)b * H_ + h] = p;
    }
}

// ---------------- launch ----------------
extern "C" void kernel_launch(void* const* d_in, const int* in_sizes, int n_in,
                              void* d_out, int out_size)
{
    const float* x      = (const float*)d_in[0];
    const float* Wp     = (const float*)d_in[1];
    const float* bp     = (const float*)d_in[2];
    const float* gp     = (const float*)d_in[3];
    const float* betap  = (const float*)d_in[4];
    const float* Ww     = (const float*)d_in[5];
    const float* bw     = (const float*)d_in[6];
    const float* gw     = (const float*)d_in[7];
    const float* betaw  = (const float*)d_in[8];
    const float* temp   = (const float*)d_in[9];
    const float* phases = (const float*)d_in[10];
    const float* Wg     = (const float*)d_in[11];
    const float* bg     = (const float*)d_in[12];
    const float* W1     = (const float*)d_in[13];
    const float* b1     = (const float*)d_in[14];
    const float* W2     = (const float*)d_in[15];
    const float* b2     = (const float*)d_in[16];
    float* out = (float*)d_out;

    float *pH, *pOut2, *pSr, *pSi, *pMa, *pMb, *pPr, *pT1, *pU, *pV, *pT;
    cudaGetSymbolAddress((void**)&pH,    d_h);
    cudaGetSymbolAddress((void**)&pOut2, d_out2);
    cudaGetSymbolAddress((void**)&pSr,   d_supr);
    cudaGetSymbolAddress((void**)&pSi,   d_supi);
    cudaGetSymbolAddress((void**)&pMa,   d_magA);
    cudaGetSymbolAddress((void**)&pMb,   d_magB);
    cudaGetSymbolAddress((void**)&pPr,   d_prob);
    cudaGetSymbolAddress((void**)&pT1,   d_t1);
    cudaGetSymbolAddress((void**)&pU,    d_su);
    cudaGetSymbolAddress((void**)&pV,    d_sv);
    cudaGetSymbolAddress((void**)&pT,    d_st);

    // 1) pre-LN projection: d_h = x @ Wp + bp
    sgemm_k<0, false><<<dim3(P_ / BN, B_ / BM, 1), 256>>>(
        x, Wp, pH, B_, P_, IN_, P_, bp, 0, 0, 0, nullptr, nullptr, nullptr);

    // 2) LN + gelu in place
    ln_gelu_k<<<B_, 256>>>(pH, gp, betap);

    // 3) spectral normalization -> d_sigma_inv
    sn_init_k<<<dim3(P_ / 256, NW_), 256>>>(pU);
    for (int it = 0; it < 5; it++) {
        sn_mv_Wu_k <<<dim3(P_ / 8,  NW_), 256>>>(Ww, pU, pV);
        sn_norm_k  <<<NW_, 256>>>(pV);
        sn_mv_WTv_k<<<dim3(P_ / 256, NW_), 256>>>(Ww, pV, pU);
        sn_norm_k  <<<NW_, 256>>>(pU);
    }
    sn_mv_Wu_k <<<dim3(P_ / 8, NW_), 256>>>(Ww, pU, pT);
    sn_sigma_k <<<NW_, 256>>>(pV, pT);

    // 4) wave GEMM (batched over 3 waves, sigma folded into epilogue):
    //    d_out2[b, s, :] = (h @ Ww[s]) * sigma_inv[s] + bw[s]
    sgemm_k<1, false><<<dim3(H2_ / BN, B_ / BM, NW_), 256>>>(
        pH, Ww, pOut2, B_, H2_, P_, NW_ * H2_, bw,
        (long long)P_ * H2_, H2_, H2_, nullptr, nullptr, nullptr);

    // 5) fused wave stage -> sup_r, sup_i, mag0
    wave_k<<<B_, 256>>>(pOut2, gw, betaw, phases, temp, pSr, pSi, pMa);

    // 6) SM_STEPS=2 gate updates (mag double-buffered)
    sgemm_k<2, false><<<dim3(H_ / BN, B_ / BM, 1), 256>>>(
        pMa, Wg, pMb, B_, H_, H_, H_, bg, 0, 0, 0, pSr, pSi, pMb);
    sgemm_k<2, false><<<dim3(H_ / BN, B_ / BM, 1), 256>>>(
        pMb, Wg, pMa, B_, H_, H_, H_, bg, 0, 0, 0, pSr, pSi, pMa);

    // 7) top-8 -> probs
    topk_k<<<B_, 256>>>(pSr, pSi, pPr);

    // 8) head: t1 = gelu(probs @ W1 + b1); out = t1 @ W2 + b2
    sgemm_k<3, false><<<dim3(H_ / BN, B_ / BM, 1), 256>>>(
        pPr, W1, pT1, B_, H_, H_, H_, b1, 0, 0, 0, nullptr, nullptr, nullptr);
    sgemm_k<0, true><<<dim3((NC_ + BN - 1) / BN, B_ / BM, 1), 256>>>(
        pT1, W2, out, B_, NC_, H_, NC_, b2, 0, 0, 0, nullptr, nullptr, nullptr);
}